// round 1
// baseline (speedup 1.0000x reference)
#include <cuda_runtime.h>
#include <math.h>

// ---------------------------------------------------------------------------
// HardCausalTemporalEncoder  (N=4096, E=512, H=8, hd=64)
//   qkv = x @ Wqkv^T + b
//   attn: per-head softmax((QK^T)/8 with step mask (-1e9)) @ V
//   x_att = ctx @ Wout^T + b
//   combined = [x_att | status_embed[mask] | time_enc[step]]   (512+128+256=896)
//   h = combined @ Wmlp^T + b ;  out = x + relu(LN(h))
// ---------------------------------------------------------------------------

#define NROWS 4096
#define EDIM  512
#define QKVLD 1536

// scratch (device globals: no allocations allowed)
__device__ float g_qkv [NROWS * QKVLD];      // 25 MB
__device__ float g_ctx [NROWS * EDIM];       // 8 MB
__device__ float g_comb[NROWS * 896];        // 14 MB
__device__ float g_h   [NROWS * EDIM];       // 8 MB
__device__ float g_te  [100 * 256];          // time encoding table

// ---------------------------------------------------------------------------
// sinusoidal time table, computed in double for fidelity to the reference
// ---------------------------------------------------------------------------
__global__ void build_te_kernel() {
    int t = blockIdx.x * blockDim.x + threadIdx.x;
    if (t >= 100 * 128) return;
    int p = t >> 7;       // step 0..99
    int k = t & 127;      // pair index 0..127
    double div = exp(-((double)(2 * k)) * log(10000.0) / 256.0);
    double ang = (double)p * div;
    g_te[p * 256 + 2 * k]     = (float)sin(ang);
    g_te[p * 256 + 2 * k + 1] = (float)cos(ang);
}

// ---------------------------------------------------------------------------
// generic SGEMM:  C[M,N] = A[M,K](lda) @ W[N,K]^T + bias   (64x64 tile, BK=16)
// grid: (N/64, M/64), block: 256 threads, 4x4 micro-tile per thread
// ---------------------------------------------------------------------------
__global__ void sgemm_bias_kernel(const float* __restrict__ A, int lda,
                                  const float* __restrict__ W,
                                  const float* __restrict__ bias,
                                  float* __restrict__ C, int ldc, int K) {
    __shared__ float As[16][65];
    __shared__ float Ws[16][65];
    const int t  = threadIdx.x;
    const int tx = t & 15, ty = t >> 4;
    const int bm = blockIdx.y * 64, bn = blockIdx.x * 64;
    float acc[4][4] = {};

    for (int k0 = 0; k0 < K; k0 += 16) {
        #pragma unroll
        for (int s = 0; s < 4; s++) {
            int e = t + 256 * s;
            int r = e >> 4, c = e & 15;
            As[c][r] = A[(bm + r) * lda + k0 + c];
            Ws[c][r] = W[(bn + r) * K   + k0 + c];
        }
        __syncthreads();
        #pragma unroll
        for (int kk = 0; kk < 16; kk++) {
            float a[4], b[4];
            #pragma unroll
            for (int i = 0; i < 4; i++) a[i] = As[kk][ty * 4 + i];
            #pragma unroll
            for (int j = 0; j < 4; j++) b[j] = Ws[kk][tx * 4 + j];
            #pragma unroll
            for (int i = 0; i < 4; i++)
                #pragma unroll
                for (int j = 0; j < 4; j++)
                    acc[i][j] += a[i] * b[j];
        }
        __syncthreads();
    }

    #pragma unroll
    for (int i = 0; i < 4; i++) {
        int r = bm + ty * 4 + i;
        #pragma unroll
        for (int j = 0; j < 4; j++) {
            int cc = bn + tx * 4 + j;
            C[r * ldc + cc] = acc[i][j] + bias[cc];
        }
    }
}

// ---------------------------------------------------------------------------
// flash-style fp32 attention with hard step mask.
// grid: (N/64, H), block 256 (16x16 threads, 4x4 micro-tiles)
// ---------------------------------------------------------------------------
__global__ void attn_kernel(const int* __restrict__ steps) {
    const int h  = blockIdx.y;
    const int qb = blockIdx.x * 64;

    __shared__ float Qs[16][65];
    __shared__ float Ks[16][65];
    __shared__ float Vs[64][65];
    __shared__ float Ss[64][65];
    __shared__ float red[64][16];
    __shared__ float mrow[64], lrow[64], arow[64];
    __shared__ int   sq[64], sk[64];

    const int t  = threadIdx.x;
    const int tx = t & 15, ty = t >> 4;
    const int row0 = ty * 4;

    if (t < 64) { mrow[t] = -1e30f; lrow[t] = 0.f; sq[t] = steps[qb + t]; }
    float acc[4][4] = {};
    __syncthreads();

    for (int kb = 0; kb < NROWS; kb += 64) {
        if (t < 64) sk[t] = steps[kb + t];

        // ---- S = Q K^T (accumulate over hd in chunks of 16) ----
        float s[4][4] = {};
        for (int d0 = 0; d0 < 64; d0 += 16) {
            #pragma unroll
            for (int si = 0; si < 4; si++) {
                int e = t + 256 * si;
                int r = e >> 4, c = e & 15;
                Qs[c][r] = g_qkv[(qb + r) * QKVLD +        h * 64 + d0 + c];
                Ks[c][r] = g_qkv[(kb + r) * QKVLD + 512  + h * 64 + d0 + c];
            }
            __syncthreads();
            #pragma unroll
            for (int kk = 0; kk < 16; kk++) {
                float a[4], b[4];
                #pragma unroll
                for (int i = 0; i < 4; i++) a[i] = Qs[kk][row0 + i];
                #pragma unroll
                for (int j = 0; j < 4; j++) b[j] = Ks[kk][tx * 4 + j];
                #pragma unroll
                for (int i = 0; i < 4; i++)
                    #pragma unroll
                    for (int j = 0; j < 4; j++)
                        s[i][j] += a[i] * b[j];
            }
            __syncthreads();
        }

        // ---- scale + mask + partial row max ----
        #pragma unroll
        for (int i = 0; i < 4; i++) {
            int qr = row0 + i;
            float mx = -1e30f;
            int sqi = sq[qr];
            #pragma unroll
            for (int j = 0; j < 4; j++) {
                float v = s[i][j] * 0.125f;
                if (sk[tx * 4 + j] < sqi) v = -1e9f;
                s[i][j] = v;
                mx = fmaxf(mx, v);
            }
            red[qr][tx] = mx;
        }
        __syncthreads();

        if (t < 64) {
            float m_old = mrow[t];
            float mx = m_old;
            #pragma unroll
            for (int c = 0; c < 16; c++) mx = fmaxf(mx, red[t][c]);
            mrow[t] = mx;
            arow[t] = __expf(m_old - mx);
        }
        __syncthreads();

        // ---- exponentiate + partial row sums; stage P into smem ----
        #pragma unroll
        for (int i = 0; i < 4; i++) {
            int qr = row0 + i;
            float m = mrow[qr];
            float ps = 0.f;
            #pragma unroll
            for (int j = 0; j < 4; j++) {
                float p = __expf(s[i][j] - m);
                Ss[qr][tx * 4 + j] = p;
                ps += p;
            }
            red[qr][tx] = ps;
        }
        __syncthreads();

        if (t < 64) {
            float sm = 0.f;
            #pragma unroll
            for (int c = 0; c < 16; c++) sm += red[t][c];
            lrow[t] = lrow[t] * arow[t] + sm;
        }

        // ---- load V tile (concurrent with lrow update; disjoint smem) ----
        #pragma unroll
        for (int si = 0; si < 16; si++) {
            int e = t + 256 * si;
            int r = e >> 6, c = e & 63;
            Vs[r][c] = g_qkv[(kb + r) * QKVLD + 1024 + h * 64 + c];
        }
        __syncthreads();

        // ---- rescale accumulator, O += P @ V ----
        float al[4];
        #pragma unroll
        for (int i = 0; i < 4; i++) al[i] = arow[row0 + i];
        #pragma unroll
        for (int i = 0; i < 4; i++)
            #pragma unroll
            for (int j = 0; j < 4; j++) acc[i][j] *= al[i];

        #pragma unroll 16
        for (int kk = 0; kk < 64; kk++) {
            float a[4], b[4];
            #pragma unroll
            for (int i = 0; i < 4; i++) a[i] = Ss[row0 + i][kk];
            #pragma unroll
            for (int j = 0; j < 4; j++) b[j] = Vs[kk][tx * 4 + j];
            #pragma unroll
            for (int i = 0; i < 4; i++)
                #pragma unroll
                for (int j = 0; j < 4; j++)
                    acc[i][j] += a[i] * b[j];
        }
        __syncthreads();
    }

    // ---- normalize and write ctx ----
    #pragma unroll
    for (int i = 0; i < 4; i++) {
        int qr = row0 + i;
        float inv = 1.f / lrow[qr];
        #pragma unroll
        for (int j = 0; j < 4; j++)
            g_ctx[(qb + qr) * EDIM + h * 64 + tx * 4 + j] = acc[i][j] * inv;
    }
}

// ---------------------------------------------------------------------------
// fill columns 512..895 of combined: status embed + time encoding
// ---------------------------------------------------------------------------
__global__ void fill_comb_kernel(const int* __restrict__ dmask,
                                 const int* __restrict__ steps,
                                 const float* __restrict__ status) {
    int row = blockIdx.x;
    int t = threadIdx.x;   // 0..383
    float v;
    if (t < 128) {
        v = status[dmask[row] * 128 + t];
    } else {
        int sc = steps[row];
        sc = sc < 0 ? 0 : (sc > 99 ? 99 : sc);
        v = g_te[sc * 256 + (t - 128)];
    }
    g_comb[row * 896 + 512 + t] = v;
}

// ---------------------------------------------------------------------------
// LayerNorm -> ReLU -> residual add.  One block (256 thr) per row; 2 elems/thr
// ---------------------------------------------------------------------------
__global__ void ln_relu_res_kernel(const float* __restrict__ x,
                                   const float* __restrict__ gamma,
                                   const float* __restrict__ beta,
                                   float* __restrict__ out) {
    int row = blockIdx.x;
    int t = threadIdx.x;
    const float* hr = g_h + row * EDIM;
    float v0 = hr[t], v1 = hr[t + 256];

    __shared__ float sh[8];
    __shared__ float stat[2];

    float s = v0 + v1;
    #pragma unroll
    for (int o = 16; o; o >>= 1) s += __shfl_xor_sync(0xffffffffu, s, o);
    if ((t & 31) == 0) sh[t >> 5] = s;
    __syncthreads();
    if (t == 0) {
        float tot = 0.f;
        #pragma unroll
        for (int i = 0; i < 8; i++) tot += sh[i];
        stat[0] = tot * (1.f / 512.f);
    }
    __syncthreads();
    float mu = stat[0];
    float d0 = v0 - mu, d1 = v1 - mu;
    float vv = d0 * d0 + d1 * d1;
    #pragma unroll
    for (int o = 16; o; o >>= 1) vv += __shfl_xor_sync(0xffffffffu, vv, o);
    if ((t & 31) == 0) sh[t >> 5] = vv;
    __syncthreads();
    if (t == 0) {
        float tot = 0.f;
        #pragma unroll
        for (int i = 0; i < 8; i++) tot += sh[i];
        stat[1] = 1.f / sqrtf(tot * (1.f / 512.f) + 1e-5f);
    }
    __syncthreads();
    float inv = stat[1];

    float y0 = fmaxf(d0 * inv * gamma[t]       + beta[t],       0.f);
    float y1 = fmaxf(d1 * inv * gamma[t + 256] + beta[t + 256], 0.f);
    out[row * EDIM + t]       = x[row * EDIM + t]       + y0;
    out[row * EDIM + t + 256] = x[row * EDIM + t + 256] + y1;
}

// ---------------------------------------------------------------------------
extern "C" void kernel_launch(void* const* d_in, const int* in_sizes, int n_in,
                              void* d_out, int out_size) {
    const float* x      = (const float*)d_in[0];
    const int*   dmask  = (const int*)  d_in[1];
    const int*   steps  = (const int*)  d_in[2];
    const float* status = (const float*)d_in[3];
    const float* wqkv   = (const float*)d_in[4];
    const float* bqkv   = (const float*)d_in[5];
    const float* wout   = (const float*)d_in[6];
    const float* bout   = (const float*)d_in[7];
    const float* wmlp   = (const float*)d_in[8];
    const float* bmlp   = (const float*)d_in[9];
    const float* gamma  = (const float*)d_in[10];
    const float* beta   = (const float*)d_in[11];
    float* out = (float*)d_out;

    float *qkv, *ctx, *comb, *hbuf;
    cudaGetSymbolAddress((void**)&qkv,  g_qkv);
    cudaGetSymbolAddress((void**)&ctx,  g_ctx);
    cudaGetSymbolAddress((void**)&comb, g_comb);
    cudaGetSymbolAddress((void**)&hbuf, g_h);

    // 1. time encoding table (deterministic, cheap)
    build_te_kernel<<<50, 256>>>();

    // 2. qkv = x @ Wqkv^T + b     [4096,512] x [1536,512]^T
    sgemm_bias_kernel<<<dim3(24, 64), 256>>>(x, 512, wqkv, bqkv, qkv, QKVLD, 512);

    // 3. attention -> ctx
    attn_kernel<<<dim3(64, 8), 256>>>(steps);

    // 4. x_att = ctx @ Wout^T + b  -> combined[:, 0:512] (ldc = 896)
    sgemm_bias_kernel<<<dim3(8, 64), 256>>>(ctx, 512, wout, bout, comb, 896, 512);

    // 5. combined[:, 512:896] = [status | time]
    fill_comb_kernel<<<4096, 384>>>(dmask, steps, status);

    // 6. h = combined @ Wmlp^T + b
    sgemm_bias_kernel<<<dim3(8, 64), 256>>>(comb, 896, wmlp, bmlp, hbuf, 512, 896);

    // 7. out = x + relu(LN(h))
    ln_relu_res_kernel<<<4096, 256>>>(x, gamma, beta, out);
}

// round 2
// speedup vs baseline: 2.4404x; 2.4404x over previous
#include <cuda_runtime.h>
#include <math.h>

#define NROWS 4096
#define EDIM  512
#define QKVLD 1536
#define PAD   68

// scratch (device globals: no allocations allowed)
__device__ float g_qkv [NROWS * QKVLD];
__device__ float g_ctx [NROWS * EDIM];
__device__ float g_comb[NROWS * 896];
__device__ float g_h   [NROWS * EDIM];
__device__ float g_te  [100 * 256];
__device__ int   g_perm  [NROWS];   // perm[r] = original row index (sorted by step)
__device__ int   g_ssteps[NROWS];   // sorted steps
__device__ int   g_kstart[64];      // first non-fully-blocked k-tile per q-tile

// ---------------------------------------------------------------------------
// sinusoidal time table (double precision for fidelity)
// ---------------------------------------------------------------------------
__global__ void build_te_kernel() {
    int t = blockIdx.x * blockDim.x + threadIdx.x;
    if (t >= 100 * 128) return;
    int p = t >> 7;
    int k = t & 127;
    double div = exp(-((double)(2 * k)) * log(10000.0) / 256.0);
    double ang = (double)p * div;
    g_te[p * 256 + 2 * k]     = (float)sin(ang);
    g_te[p * 256 + 2 * k + 1] = (float)cos(ang);
}

// ---------------------------------------------------------------------------
// deterministic counting sort of rows by step + per-qtile kstart
// single block, 128 threads
// ---------------------------------------------------------------------------
__global__ void sort_kernel(const int* __restrict__ steps) {
    __shared__ int s_steps[NROWS];
    __shared__ int hist[100];
    __shared__ int base[100];
    const int t = threadIdx.x;

    for (int i = t; i < 100; i += 128) hist[i] = 0;
    __syncthreads();
    for (int i = t; i < NROWS; i += 128) {
        int s = steps[i];
        s = s < 0 ? 0 : (s > 99 ? 99 : s);
        s_steps[i] = s;
        atomicAdd(&hist[s], 1);
    }
    __syncthreads();
    if (t == 0) {
        int acc = 0;
        for (int b = 0; b < 100; b++) { base[b] = acc; acc += hist[b]; }
    }
    __syncthreads();
    if (t < 100) {                       // stable per-bucket scan (deterministic)
        int r = base[t];
        for (int i = 0; i < NROWS; i++) {
            if (s_steps[i] == t) {
                g_perm[r] = i;
                g_ssteps[r] = t;
                r++;
            }
        }
    }
    __syncthreads();
    if (t < 64) {                        // kstart: first kt with tile-max >= qtile-min
        int qmin = g_ssteps[t * 64];
        int ks = 0;
        while (ks < 64 && g_ssteps[ks * 64 + 63] < qmin) ks++;
        g_kstart[t] = ks;
    }
}

// ---------------------------------------------------------------------------
// SGEMM  C[M,N] = A[M,K] @ W[N,K]^T + bias
// 64x64 tile, BK=32, block 128, 8x4 micro-tile, reg-staged prefetch,
// W transposed into smem with conflict-free XOR swizzle on float4 groups.
// ---------------------------------------------------------------------------
__global__ __launch_bounds__(128)
void sgemm_bias_kernel(const float* __restrict__ A, int lda,
                       const float* __restrict__ W,
                       const float* __restrict__ bias,
                       float* __restrict__ C, int ldc, int K) {
    __shared__ float As[64][36];     // [m][k]
    __shared__ float WT[32][PAD];    // [k][n swizzled]
    const int t  = threadIdx.x;
    const int tx = t & 15, tg = t >> 4;
    const int r0 = tg * 8;
    const int bm = blockIdx.y * 64, bn = blockIdx.x * 64;

    int mReg[4], cReg[4];
    #pragma unroll
    for (int s = 0; s < 4; s++) {
        int flat = t + 128 * s;
        mReg[s] = flat >> 3;
        cReg[s] = flat & 7;
    }

    float4 pa[4], pw[4];
    #pragma unroll
    for (int s = 0; s < 4; s++) {
        pa[s] = *(const float4*)(A + (size_t)(bm + mReg[s]) * lda + cReg[s] * 4);
        pw[s] = *(const float4*)(W + (size_t)(bn + mReg[s]) * K   + cReg[s] * 4);
    }

    float acc[8][4] = {};
    const int nck = K >> 5;
    for (int c = 0; c < nck; c++) {
        #pragma unroll
        for (int s = 0; s < 4; s++) {
            *(float4*)&As[mReg[s]][cReg[s] * 4] = pa[s];
            int n = mReg[s];
            #pragma unroll
            for (int u = 0; u < 4; u++) {
                int k  = cReg[s] * 4 + u;
                int ns = ((((n >> 2) ^ ((k >> 2) & 7)) << 2) | (n & 3));
                WT[k][ns] = (&pw[s].x)[u];
            }
        }
        __syncthreads();
        if (c + 1 < nck) {
            int k0 = (c + 1) << 5;
            #pragma unroll
            for (int s = 0; s < 4; s++) {
                pa[s] = *(const float4*)(A + (size_t)(bm + mReg[s]) * lda + k0 + cReg[s] * 4);
                pw[s] = *(const float4*)(W + (size_t)(bn + mReg[s]) * K   + k0 + cReg[s] * 4);
            }
        }
        #pragma unroll 2
        for (int kk = 0; kk < 32; kk += 4) {
            float4 b4[4];
            const int fs = (tx ^ ((kk >> 2) & 7)) << 2;
            #pragma unroll
            for (int u = 0; u < 4; u++)
                b4[u] = *(const float4*)&WT[kk + u][fs];
            #pragma unroll
            for (int i = 0; i < 8; i++) {
                float4 a = *(const float4*)&As[r0 + i][kk];
                #pragma unroll
                for (int u = 0; u < 4; u++) {
                    float av = (&a.x)[u];
                    acc[i][0] += av * b4[u].x;
                    acc[i][1] += av * b4[u].y;
                    acc[i][2] += av * b4[u].z;
                    acc[i][3] += av * b4[u].w;
                }
            }
        }
        __syncthreads();
    }

    float4 bb = *(const float4*)(bias + bn + tx * 4);
    #pragma unroll
    for (int i = 0; i < 8; i++) {
        float4 o;
        o.x = acc[i][0] + bb.x;
        o.y = acc[i][1] + bb.y;
        o.z = acc[i][2] + bb.z;
        o.w = acc[i][3] + bb.w;
        *(float4*)(C + (size_t)(bm + r0 + i) * ldc + bn + tx * 4) = o;
    }
}

// ---------------------------------------------------------------------------
// flash attention in sorted space with fully-blocked-tile skipping.
// grid (64 qtiles, 8 heads), block 128, 8x4 micro-tiles.
// Q kept resident (transposed+swizzled) for the whole block.
// ---------------------------------------------------------------------------
__global__ __launch_bounds__(128)
void attn_kernel() {
    extern __shared__ float smdyn[];
    float* QT = smdyn;                 // [k][q swizzled]
    float* Ks = smdyn + 64 * PAD;      // [key][d]
    float* Vs = smdyn + 2 * 64 * PAD;  // [key][d]
    float* Ss = smdyn + 3 * 64 * PAD;  // [key][q]  (P^T)
    __shared__ float red[64][9];
    __shared__ float m_s[64], l_s[64], alpha_s[64];
    __shared__ int sks[64], sqs[64], qperm[64];

    const int h  = blockIdx.y;
    const int qt = blockIdx.x;
    const int qb = qt * 64;
    const int t  = threadIdx.x;
    const int tx = t & 15, tg = t >> 4;
    const int r0 = tg * 8;

    if (t < 64) {
        qperm[t] = g_perm[qb + t];
        sqs[t]   = g_ssteps[qb + t];
        m_s[t]   = -1e30f;
        l_s[t]   = 0.f;
    }
    __syncthreads();

    // Q tile, transposed into QT[k][swz(q,k)] (paid once per block)
    #pragma unroll
    for (int it = 0; it < 8; it++) {
        int i = t + 128 * it;
        int q = i >> 4, c4 = i & 15;
        float4 v = *(const float4*)(g_qkv + (size_t)qperm[q] * QKVLD + h * 64 + c4 * 4);
        #pragma unroll
        for (int u = 0; u < 4; u++) {
            int k  = c4 * 4 + u;
            int qs = ((((q >> 2) ^ ((k >> 2) & 7)) << 2) | (q & 3));
            QT[k * PAD + qs] = (&v.x)[u];
        }
    }

    int sq4[4];
    #pragma unroll
    for (int j = 0; j < 4; j++) sq4[j] = sqs[tx * 4 + j];

    float acc[8][4] = {};
    const int kstart = g_kstart[qt];

    for (int kt = kstart; kt < 64; kt++) {
        const int kb = kt * 64;
        __syncthreads();   // (A) publish QT / protect Ks,Vs,Ss reuse

        #pragma unroll
        for (int it = 0; it < 8; it++) {
            int i = t + 128 * it;
            int key = i >> 4, c4 = i & 15;
            const float* rp = g_qkv + (size_t)g_perm[kb + key] * QKVLD + h * 64 + c4 * 4;
            *(float4*)(Ks + key * PAD + c4 * 4) = *(const float4*)(rp + 512);
            *(float4*)(Vs + key * PAD + c4 * 4) = *(const float4*)(rp + 1024);
        }
        if (t < 64) sks[t] = g_ssteps[kb + t];
        __syncthreads();   // (B)

        // S^T[key=r0+i][q=4tx+j] = K . Q
        float sT[8][4] = {};
        #pragma unroll 1
        for (int kk = 0; kk < 64; kk += 4) {
            float4 b4[4];
            const int fs = (tx ^ ((kk >> 2) & 7)) << 2;
            #pragma unroll
            for (int u = 0; u < 4; u++)
                b4[u] = *(const float4*)(QT + (kk + u) * PAD + fs);
            #pragma unroll
            for (int i = 0; i < 8; i++) {
                float4 a = *(const float4*)(Ks + (r0 + i) * PAD + kk);
                #pragma unroll
                for (int u = 0; u < 4; u++) {
                    float av = (&a.x)[u];
                    sT[i][0] += av * b4[u].x;
                    sT[i][1] += av * b4[u].y;
                    sT[i][2] += av * b4[u].z;
                    sT[i][3] += av * b4[u].w;
                }
            }
        }

        // scale + mask + per-q partial max over this thread's 8 keys
        int sk8[8];
        #pragma unroll
        for (int i = 0; i < 8; i++) sk8[i] = sks[r0 + i];
        float pmax[4] = {-1e30f, -1e30f, -1e30f, -1e30f};
        #pragma unroll
        for (int i = 0; i < 8; i++)
            #pragma unroll
            for (int j = 0; j < 4; j++) {
                float v = sT[i][j] * 0.125f;
                if (sk8[i] < sq4[j]) v = -1e9f;
                sT[i][j] = v;
                pmax[j] = fmaxf(pmax[j], v);
            }
        #pragma unroll
        for (int j = 0; j < 4; j++) red[tx * 4 + j][tg] = pmax[j];
        __syncthreads();   // (C)

        if (t < 64) {
            float mo = m_s[t], mx = mo;
            #pragma unroll
            for (int c = 0; c < 8; c++) mx = fmaxf(mx, red[t][c]);
            m_s[t] = mx;
            alpha_s[t] = __expf(mo - mx);
        }
        __syncthreads();   // (D)

        float mj[4], psum[4] = {0.f, 0.f, 0.f, 0.f};
        #pragma unroll
        for (int j = 0; j < 4; j++) mj[j] = m_s[tx * 4 + j];
        #pragma unroll
        for (int i = 0; i < 8; i++) {
            float4 w;
            w.x = __expf(sT[i][0] - mj[0]); psum[0] += w.x;
            w.y = __expf(sT[i][1] - mj[1]); psum[1] += w.y;
            w.z = __expf(sT[i][2] - mj[2]); psum[2] += w.z;
            w.w = __expf(sT[i][3] - mj[3]); psum[3] += w.w;
            *(float4*)(Ss + (r0 + i) * PAD + tx * 4) = w;
        }
        #pragma unroll
        for (int j = 0; j < 4; j++) red[tx * 4 + j][tg] = psum[j];
        __syncthreads();   // (E)

        if (t < 64) {
            float s = 0.f;
            #pragma unroll
            for (int c = 0; c < 8; c++) s += red[t][c];
            l_s[t] = l_s[t] * alpha_s[t] + s;
        }

        // rescale accumulator, O += P @ V  (O[q=r0+i][d=4tx+j])
        float av8[8];
        #pragma unroll
        for (int i = 0; i < 8; i++) av8[i] = alpha_s[r0 + i];
        #pragma unroll
        for (int i = 0; i < 8; i++)
            #pragma unroll
            for (int j = 0; j < 4; j++) acc[i][j] *= av8[i];

        #pragma unroll 4
        for (int kk = 0; kk < 64; kk++) {
            float4 aA = *(const float4*)(Ss + kk * PAD + r0);
            float4 aB = *(const float4*)(Ss + kk * PAD + r0 + 4);
            float4 bv = *(const float4*)(Vs + kk * PAD + tx * 4);
            acc[0][0] += aA.x * bv.x; acc[0][1] += aA.x * bv.y; acc[0][2] += aA.x * bv.z; acc[0][3] += aA.x * bv.w;
            acc[1][0] += aA.y * bv.x; acc[1][1] += aA.y * bv.y; acc[1][2] += aA.y * bv.z; acc[1][3] += aA.y * bv.w;
            acc[2][0] += aA.z * bv.x; acc[2][1] += aA.z * bv.y; acc[2][2] += aA.z * bv.z; acc[2][3] += aA.z * bv.w;
            acc[3][0] += aA.w * bv.x; acc[3][1] += aA.w * bv.y; acc[3][2] += aA.w * bv.z; acc[3][3] += aA.w * bv.w;
            acc[4][0] += aB.x * bv.x; acc[4][1] += aB.x * bv.y; acc[4][2] += aB.x * bv.z; acc[4][3] += aB.x * bv.w;
            acc[5][0] += aB.y * bv.x; acc[5][1] += aB.y * bv.y; acc[5][2] += aB.y * bv.z; acc[5][3] += aB.y * bv.w;
            acc[6][0] += aB.z * bv.x; acc[6][1] += aB.z * bv.y; acc[6][2] += aB.z * bv.z; acc[6][3] += aB.z * bv.w;
            acc[7][0] += aB.w * bv.x; acc[7][1] += aB.w * bv.y; acc[7][2] += aB.w * bv.z; acc[7][3] += aB.w * bv.w;
        }
    }
    __syncthreads();

    float linv[8];
    #pragma unroll
    for (int i = 0; i < 8; i++) linv[i] = 1.f / l_s[r0 + i];
    #pragma unroll
    for (int i = 0; i < 8; i++) {
        float4 o;
        o.x = acc[i][0] * linv[i];
        o.y = acc[i][1] * linv[i];
        o.z = acc[i][2] * linv[i];
        o.w = acc[i][3] * linv[i];
        *(float4*)(g_ctx + (size_t)qperm[r0 + i] * EDIM + h * 64 + tx * 4) = o;
    }
}

// ---------------------------------------------------------------------------
// fill columns 512..895 of combined: status embed + time encoding
// ---------------------------------------------------------------------------
__global__ void fill_comb_kernel(const int* __restrict__ dmask,
                                 const int* __restrict__ steps,
                                 const float* __restrict__ status) {
    int row = blockIdx.x;
    int t = threadIdx.x;   // 0..383
    float v;
    if (t < 128) {
        v = status[dmask[row] * 128 + t];
    } else {
        int sc = steps[row];
        sc = sc < 0 ? 0 : (sc > 99 ? 99 : sc);
        v = g_te[sc * 256 + (t - 128)];
    }
    g_comb[row * 896 + 512 + t] = v;
}

// ---------------------------------------------------------------------------
// LayerNorm -> ReLU -> residual add
// ---------------------------------------------------------------------------
__global__ void ln_relu_res_kernel(const float* __restrict__ x,
                                   const float* __restrict__ gamma,
                                   const float* __restrict__ beta,
                                   float* __restrict__ out) {
    int row = blockIdx.x;
    int t = threadIdx.x;
    const float* hr = g_h + row * EDIM;
    float v0 = hr[t], v1 = hr[t + 256];

    __shared__ float sh[8];
    __shared__ float stat[2];

    float s = v0 + v1;
    #pragma unroll
    for (int o = 16; o; o >>= 1) s += __shfl_xor_sync(0xffffffffu, s, o);
    if ((t & 31) == 0) sh[t >> 5] = s;
    __syncthreads();
    if (t == 0) {
        float tot = 0.f;
        #pragma unroll
        for (int i = 0; i < 8; i++) tot += sh[i];
        stat[0] = tot * (1.f / 512.f);
    }
    __syncthreads();
    float mu = stat[0];
    float d0 = v0 - mu, d1 = v1 - mu;
    float vv = d0 * d0 + d1 * d1;
    #pragma unroll
    for (int o = 16; o; o >>= 1) vv += __shfl_xor_sync(0xffffffffu, vv, o);
    if ((t & 31) == 0) sh[t >> 5] = vv;
    __syncthreads();
    if (t == 0) {
        float tot = 0.f;
        #pragma unroll
        for (int i = 0; i < 8; i++) tot += sh[i];
        stat[1] = 1.f / sqrtf(tot * (1.f / 512.f) + 1e-5f);
    }
    __syncthreads();
    float inv = stat[1];

    float y0 = fmaxf(d0 * inv * gamma[t]       + beta[t],       0.f);
    float y1 = fmaxf(d1 * inv * gamma[t + 256] + beta[t + 256], 0.f);
    out[row * EDIM + t]       = x[row * EDIM + t]       + y0;
    out[row * EDIM + t + 256] = x[row * EDIM + t + 256] + y1;
}

// ---------------------------------------------------------------------------
extern "C" void kernel_launch(void* const* d_in, const int* in_sizes, int n_in,
                              void* d_out, int out_size) {
    const float* x      = (const float*)d_in[0];
    const int*   dmask  = (const int*)  d_in[1];
    const int*   steps  = (const int*)  d_in[2];
    const float* status = (const float*)d_in[3];
    const float* wqkv   = (const float*)d_in[4];
    const float* bqkv   = (const float*)d_in[5];
    const float* wout   = (const float*)d_in[6];
    const float* bout   = (const float*)d_in[7];
    const float* wmlp   = (const float*)d_in[8];
    const float* bmlp   = (const float*)d_in[9];
    const float* gamma  = (const float*)d_in[10];
    const float* beta   = (const float*)d_in[11];
    float* out = (float*)d_out;

    float *qkv, *ctx, *comb, *hbuf;
    cudaGetSymbolAddress((void**)&qkv,  g_qkv);
    cudaGetSymbolAddress((void**)&ctx,  g_ctx);
    cudaGetSymbolAddress((void**)&comb, g_comb);
    cudaGetSymbolAddress((void**)&hbuf, g_h);

    const int attn_smem = 4 * 64 * PAD * sizeof(float);   // 69632
    cudaFuncSetAttribute(attn_kernel, cudaFuncAttributeMaxDynamicSharedMemorySize,
                         attn_smem);

    // 1. sort rows by step + time table (independent, cheap)
    sort_kernel<<<1, 128>>>(steps);
    build_te_kernel<<<50, 256>>>();

    // 2. qkv = x @ Wqkv^T + b
    sgemm_bias_kernel<<<dim3(24, 64), 128>>>(x, 512, wqkv, bqkv, qkv, QKVLD, 512);

    // 3. attention (sorted space, tile skipping) -> ctx
    attn_kernel<<<dim3(64, 8), 128, attn_smem>>>();

    // 4. x_att = ctx @ Wout^T + b  -> combined[:, 0:512]
    sgemm_bias_kernel<<<dim3(8, 64), 128>>>(ctx, 512, wout, bout, comb, 896, 512);

    // 5. combined[:, 512:896] = [status | time]
    fill_comb_kernel<<<4096, 384>>>(dmask, steps, status);

    // 6. h = combined @ Wmlp^T + b
    sgemm_bias_kernel<<<dim3(8, 64), 128>>>(comb, 896, wmlp, bmlp, hbuf, 512, 896);

    // 7. out = x + relu(LN(h))
    ln_relu_res_kernel<<<4096, 256>>>(x, gamma, beta, out);
}